// round 3
// baseline (speedup 1.0000x reference)
#include <cuda_runtime.h>

#define BATCH 4
#define NPTS 8192
#define PAD 32
#define STRIDE (NPTS + 2 * PAD)
#define SORT_THREADS 1024
#define NN_THREADS 128
#define NN_BLOCKS_X (NPTS / NN_THREADS)     // 64
#define NN_BLOCKS (NN_BLOCKS_X * 8)         // 512
#define FULLMASK 0xffffffffu

// Sorted point quads per (set,batch): (x, y, z, |p|^2), padded with sentinels.
__device__ float4 g_pts[8][STRIDE];
__device__ float g_bsum[NN_BLOCKS];
__device__ unsigned g_count;   // zero-init; reset by last block each run

__device__ __forceinline__ unsigned mono(float f) {
    unsigned u = __float_as_uint(f);
    return (u & 0x80000000u) ? ~u : (u | 0x80000000u);
}

// ---------------------------------------------------------------------------
// Bitonic sort by x per (set,batch); emits sorted quads + sentinel pads.
// ---------------------------------------------------------------------------
__global__ __launch_bounds__(SORT_THREADS)
void sort_kernel(const float* __restrict__ p1, const float* __restrict__ p2) {
    __shared__ unsigned sk[NPTS];          // 32 KB  (monotone x keys)
    __shared__ unsigned short si[NPTS];    // 16 KB  (payload indices)
    const int set = blockIdx.x >> 2;
    const int b = blockIdx.x & 3;
    const float* __restrict__ P = (set ? p2 : p1) + (size_t)b * NPTS * 3;

    for (int i = threadIdx.x; i < NPTS; i += SORT_THREADS) {
        sk[i] = mono(P[3 * i]);
        si[i] = (unsigned short)i;
    }
    __syncthreads();

    for (int k = 2; k <= NPTS; k <<= 1) {
        for (int j = k >> 1; j > 0; j >>= 1) {
            for (int i = threadIdx.x; i < NPTS; i += SORT_THREADS) {
                int ixj = i ^ j;
                if (ixj > i) {
                    unsigned a = sk[i], c = sk[ixj];
                    bool up = ((i & k) == 0);
                    if ((a > c) == up) {
                        sk[i] = c; sk[ixj] = a;
                        unsigned short t = si[i]; si[i] = si[ixj]; si[ixj] = t;
                    }
                }
            }
            __syncthreads();
        }
    }

    float4* dst = g_pts[blockIdx.x];
    for (int i = threadIdx.x; i < NPTS; i += SORT_THREADS) {
        int o = si[i];
        float x = P[3 * o], y = P[3 * o + 1], z = P[3 * o + 2];
        dst[PAD + i] = make_float4(x, y, z, x * x + y * y + z * z);
    }
    // Sentinels: far-away x forces side termination; huge |t|^2 keeps min intact.
    for (int i = threadIdx.x; i < PAD; i += SORT_THREADS) {
        dst[i]              = make_float4(-1e30f, 0.f, 0.f, 3.0e38f);
        dst[PAD + NPTS + i] = make_float4( 1e30f, 0.f, 0.f, 3.0e38f);
    }
}

// ---------------------------------------------------------------------------
// Warp-cooperative expanding NN search over x-sorted targets (exact).
// ---------------------------------------------------------------------------
__global__ __launch_bounds__(NN_THREADS)
void nn_kernel(float* __restrict__ out) {
    const int db  = blockIdx.y;            // dir*4 + b
    const int dir = db >> 2, b = db & 3;
    const float4* __restrict__ Q = g_pts[(dir ? 4 : 0) + b];
    const float4* __restrict__ T = g_pts[(dir ? 0 : 4) + b];

    const int qi = blockIdx.x * NN_THREADS + threadIdx.x;
    float4 q = Q[PAD + qi];
    const float qx  = q.x;
    const float m2x = -2.f * q.x, m2y = -2.f * q.y, m2z = -2.f * q.z;
    const float qsq = q.w;

    // Warp-uniform binary search (lower bound) on median lane's x.
    const float xmid = __shfl_sync(FULLMASK, qx, 16);
    int lo = 0, hi = NPTS;
#pragma unroll
    for (int s = 0; s < 13; s++) {
        int mid = (lo + hi) >> 1;
        if (T[PAD + mid].x < xmid) lo = mid + 1; else hi = mid;
    }

    int wl = PAD + lo, wr = PAD + lo;      // window [wl, wr)
    float bestv = 3.0e38f;                 // min of (|t|^2 - 2 q.t)
    bool rdone = false, ldone = false;

    while (!(rdone && ldone)) {
        if (!rdone) {
#pragma unroll 8
            for (int j = 0; j < 32; j++) {
                float4 t = T[wr + j];      // warp-uniform broadcast load
                bestv = fminf(bestv,
                    fmaf(m2x, t.x, fmaf(m2y, t.y, fmaf(m2z, t.z, t.w))));
            }
            wr += 32;
            float dx = T[wr - 1].x - qx;
            rdone = __all_sync(FULLMASK, (dx > 0.f) && (dx * dx >= bestv + qsq));
        }
        if (!ldone) {
            wl -= 32;
#pragma unroll 8
            for (int j = 0; j < 32; j++) {
                float4 t = T[wl + j];
                bestv = fminf(bestv,
                    fmaf(m2x, t.x, fmaf(m2y, t.y, fmaf(m2z, t.z, t.w))));
            }
            float dx = qx - T[wl].x;
            ldone = __all_sync(FULLMASK, (dx > 0.f) && (dx * dx >= bestv + qsq));
        }
    }

    float d2 = bestv + qsq;                // exact min squared distance

    // Block reduction -> g_bsum; last block reduces all partials (deterministic).
    __shared__ float sred[4];
    __shared__ bool s_last;
#pragma unroll
    for (int o = 16; o; o >>= 1) d2 += __shfl_down_sync(FULLMASK, d2, o);
    if ((threadIdx.x & 31) == 0) sred[threadIdx.x >> 5] = d2;
    __syncthreads();
    if (threadIdx.x == 0) {
        float w = sred[0] + sred[1] + sred[2] + sred[3];
        g_bsum[db * NN_BLOCKS_X + blockIdx.x] = w;
        __threadfence();
        unsigned t = atomicAdd(&g_count, 1u);
        s_last = (t == NN_BLOCKS - 1);
    }
    __syncthreads();

    if (s_last) {
        __threadfence();
        float w = 0.f;
#pragma unroll
        for (int i = 0; i < NN_BLOCKS / NN_THREADS; i++)     // 4 each
            w += g_bsum[threadIdx.x + i * NN_THREADS];
#pragma unroll
        for (int o = 16; o; o >>= 1) w += __shfl_down_sync(FULLMASK, w, o);
        if ((threadIdx.x & 31) == 0) sred[threadIdx.x >> 5] = w;
        __syncthreads();
        if (threadIdx.x == 0) {
            out[0] = sred[0] + sred[1] + sred[2] + sred[3];
            g_count = 0u;                  // reset for next graph replay
        }
    }
}

extern "C" void kernel_launch(void* const* d_in, const int* in_sizes, int n_in,
                              void* d_out, int out_size) {
    const float* p1 = (const float*)d_in[0];
    const float* p2 = (const float*)d_in[1];
    float* out = (float*)d_out;

    sort_kernel<<<8, SORT_THREADS>>>(p1, p2);
    nn_kernel<<<dim3(NN_BLOCKS_X, 8), NN_THREADS>>>(out);
}

// round 4
// speedup vs baseline: 3.0743x; 3.0743x over previous
#include <cuda_runtime.h>

#define BATCH 4
#define NPTS 8192
#define PAD 32
#define STRIDE (NPTS + 2 * PAD)
#define BINS 8192
#define SORT_THREADS 1024
#define W 2048
#define NN_THREADS 128
#define NN_BLOCKS_X (NPTS / NN_THREADS)     // 64
#define NN_BLOCKS (NN_BLOCKS_X * 8)         // 512
#define FULLMASK 0xffffffffu
#define DELTA 0.005f   // >= bucket width (12/8192 = 0.00147); cert margin

// Sorted (by quantized x) point quads per (set,batch): (x,y,z,|p|^2) + sentinels.
__device__ float4 g_pts[8][STRIDE];
__device__ float g_bsum[NN_BLOCKS];
__device__ unsigned g_count;   // zero-init; reset by last block each run

__device__ __forceinline__ int bucket(float x) {
    int b = (int)((x + 6.0f) * (BINS / 12.0f));
    return min(max(b, 0), BINS - 1);
}

// ---------------------------------------------------------------------------
// Counting sort by 13-bit quantized x. O(N), one block per (set,batch).
// ---------------------------------------------------------------------------
__global__ __launch_bounds__(SORT_THREADS)
void sort_kernel(const float* __restrict__ p1, const float* __restrict__ p2) {
    __shared__ unsigned hist[BINS];        // 32 KB
    __shared__ unsigned wtot[32];
    const int tid = threadIdx.x, lane = tid & 31, wid = tid >> 5;
    const int set = blockIdx.x >> 2;
    const int b = blockIdx.x & 3;
    const float* __restrict__ P = (set ? p2 : p1) + (size_t)b * NPTS * 3;

    for (int i = tid; i < BINS; i += SORT_THREADS) hist[i] = 0;
    __syncthreads();

    // Pass 1: histogram
    for (int i = tid; i < NPTS; i += SORT_THREADS)
        atomicAdd(&hist[bucket(P[3 * i])], 1u);
    __syncthreads();

    // Exclusive scan of hist[8192]: 8 bins/thread + block scan of thread sums.
    const int base = tid * 8;
    unsigned loc[8], s = 0;
#pragma unroll
    for (int j = 0; j < 8; j++) { loc[j] = s; s += hist[base + j]; }
    unsigned v = s;
#pragma unroll
    for (int o = 1; o < 32; o <<= 1) {
        unsigned n = __shfl_up_sync(FULLMASK, v, o);
        if (lane >= o) v += n;
    }
    if (lane == 31) wtot[wid] = v;
    __syncthreads();
    if (tid < 32) {
        unsigned w = wtot[tid];
#pragma unroll
        for (int o = 1; o < 32; o <<= 1) {
            unsigned n = __shfl_up_sync(FULLMASK, w, o);
            if (tid >= o) w += n;
        }
        wtot[tid] = w;                      // inclusive warp totals
    }
    __syncthreads();
    unsigned thr_excl = v - s + (wid ? wtot[wid - 1] : 0u);
    __syncthreads();
#pragma unroll
    for (int j = 0; j < 8; j++) hist[base + j] = thr_excl + loc[j];
    __syncthreads();

    // Pass 2: scatter quads directly to sorted positions.
    float4* dst = g_pts[blockIdx.x];
    for (int i = tid; i < NPTS; i += SORT_THREADS) {
        float x = P[3 * i], y = P[3 * i + 1], z = P[3 * i + 2];
        unsigned pos = atomicAdd(&hist[bucket(x)], 1u);
        dst[PAD + pos] = make_float4(x, y, z, x * x + y * y + z * z);
    }
    // Sentinels terminate any global fallback scan.
    for (int i = tid; i < PAD; i += SORT_THREADS) {
        dst[i]              = make_float4(-1e30f, 0.f, 0.f, 3.0e38f);
        dst[PAD + NPTS + i] = make_float4( 1e30f, 0.f, 0.f, 3.0e38f);
    }
}

// ---------------------------------------------------------------------------
// NN: block-staged smem window + warp-cooperative center-out expansion.
// ---------------------------------------------------------------------------
__global__ __launch_bounds__(NN_THREADS)
void nn_kernel(float* __restrict__ out) {
    __shared__ __align__(16) float4 s_win[W];   // 32 KB
    __shared__ float sred[4];
    __shared__ bool s_last;

    const int db  = blockIdx.y;            // dir*4 + b
    const int dir = db >> 2, b = db & 3;
    const float4* __restrict__ Q = g_pts[(dir ? 4 : 0) + b];
    const float4* __restrict__ T = g_pts[(dir ? 0 : 4) + b];

    const int qi = blockIdx.x * NN_THREADS + threadIdx.x;
    const float4 q = Q[PAD + qi];
    const float qx  = q.x, qsq = q.w;
    const float m2x = -2.f * q.x, m2y = -2.f * q.y, m2z = -2.f * q.z;

    // Block-uniform window placement: binary search for block-mid query x.
    const float xmid = Q[PAD + blockIdx.x * NN_THREADS + NN_THREADS / 2].x;
    int lo = 0, hi = NPTS;
#pragma unroll
    for (int s = 0; s < 13; s++) {
        int mid = (lo + hi) >> 1;
        if (T[PAD + mid].x < xmid) lo = mid + 1; else hi = mid;
    }
    int wstart = lo - W / 2;
    wstart = min(max(wstart, 0), NPTS - W);

    for (int i = threadIdx.x; i < W; i += NN_THREADS)
        s_win[i] = T[PAD + wstart + i];
    __syncthreads();

    // Per-warp center inside the window.
    const float xw = __shfl_sync(FULLMASK, qx, 16);
    int l2 = 0, h2 = W;
#pragma unroll
    for (int s = 0; s < 11; s++) {
        int mid = (l2 + h2) >> 1;
        if (s_win[mid].x < xw) l2 = mid + 1; else h2 = mid;
    }

    int pl = l2, pr = l2;
    float bestv = 3.0e38f;                 // min of (|t|^2 - 2 q.t)
    bool rdone = false, ldone = false, gr = false, gl = false;

    while (!(rdone && ldone)) {
        if (!rdone) {
            if (pr + 32 > W) { gr = true; rdone = true; }
            else {
                float lx = 0.f;
#pragma unroll
                for (int j = 0; j < 32; j++) {
                    float4 t = s_win[pr + j];
                    bestv = fminf(bestv,
                        fmaf(m2x, t.x, fmaf(m2y, t.y, fmaf(m2z, t.z, t.w))));
                    if (j == 31) lx = t.x;
                }
                pr += 32;
                float tt = lx - qx - DELTA;
                rdone = __all_sync(FULLMASK, (tt > 0.f) && (tt * tt >= bestv + qsq));
            }
        }
        if (!ldone) {
            if (pl < 32) { gl = true; ldone = true; }
            else {
                pl -= 32;
                float fx = 0.f;
#pragma unroll
                for (int j = 0; j < 32; j++) {
                    float4 t = s_win[pl + j];
                    bestv = fminf(bestv,
                        fmaf(m2x, t.x, fmaf(m2y, t.y, fmaf(m2z, t.z, t.w))));
                    if (j == 0) fx = t.x;
                }
                float tt = qx - fx - DELTA;
                ldone = __all_sync(FULLMASK, (tt > 0.f) && (tt * tt >= bestv + qsq));
            }
        }
    }

    // Rare global continuations (window too small for this warp's worst lane).
    int gpr = wstart + pr;
    while (gr) {
        float lx = 0.f;
#pragma unroll
        for (int j = 0; j < 32; j++) {
            float4 t = T[PAD + gpr + j];
            bestv = fminf(bestv,
                fmaf(m2x, t.x, fmaf(m2y, t.y, fmaf(m2z, t.z, t.w))));
            if (j == 31) lx = t.x;
        }
        gpr += 32;
        float tt = lx - qx - DELTA;
        gr = !__all_sync(FULLMASK, (tt > 0.f) && (tt * tt >= bestv + qsq));
    }
    int gpl = wstart + pl;
    while (gl) {
        gpl -= 32;
        float fx = 0.f;
#pragma unroll
        for (int j = 0; j < 32; j++) {
            float4 t = T[PAD + gpl + j];
            bestv = fminf(bestv,
                fmaf(m2x, t.x, fmaf(m2y, t.y, fmaf(m2z, t.z, t.w))));
            if (j == 0) fx = t.x;
        }
        float tt = qx - fx - DELTA;
        gl = !__all_sync(FULLMASK, (tt > 0.f) && (tt * tt >= bestv + qsq));
    }

    float d2 = bestv + qsq;                // exact min squared distance

    // Reduction: block partials, last block folds everything.
#pragma unroll
    for (int o = 16; o; o >>= 1) d2 += __shfl_down_sync(FULLMASK, d2, o);
    if ((threadIdx.x & 31) == 0) sred[threadIdx.x >> 5] = d2;
    __syncthreads();
    if (threadIdx.x == 0) {
        g_bsum[db * NN_BLOCKS_X + blockIdx.x] = sred[0] + sred[1] + sred[2] + sred[3];
        __threadfence();
        unsigned t = atomicAdd(&g_count, 1u);
        s_last = (t == NN_BLOCKS - 1);
    }
    __syncthreads();

    if (s_last) {
        __threadfence();
        float w = 0.f;
#pragma unroll
        for (int i = 0; i < NN_BLOCKS / NN_THREADS; i++)
            w += g_bsum[threadIdx.x + i * NN_THREADS];
#pragma unroll
        for (int o = 16; o; o >>= 1) w += __shfl_down_sync(FULLMASK, w, o);
        if ((threadIdx.x & 31) == 0) sred[threadIdx.x >> 5] = w;
        __syncthreads();
        if (threadIdx.x == 0) {
            out[0] = sred[0] + sred[1] + sred[2] + sred[3];
            g_count = 0u;                  // reset for next graph replay
        }
    }
}

extern "C" void kernel_launch(void* const* d_in, const int* in_sizes, int n_in,
                              void* d_out, int out_size) {
    const float* p1 = (const float*)d_in[0];
    const float* p2 = (const float*)d_in[1];
    float* out = (float*)d_out;

    sort_kernel<<<8, SORT_THREADS>>>(p1, p2);
    nn_kernel<<<dim3(NN_BLOCKS_X, 8), NN_THREADS>>>(out);
}